// round 3
// baseline (speedup 1.0000x reference)
#include <cuda_runtime.h>
#include <math.h>

#define N_NODES  50000
#define N_EDGES  800000
#define N_GRAPHS 512
#define IN_F     128
#define OUT_F    64
#define NEG_SLOPE 0.2f

// ---------------- scratch (static device globals; no allocation) ----------------
__device__ float d_h [N_NODES * OUT_F];   // x @ W
__device__ float d_as[N_NODES * 8];       // per-node per-head src attention
__device__ float d_ad[N_NODES * 8];       // per-node per-head dst attention
__device__ int   d_deg[N_NODES];
__device__ int   d_off[N_NODES + 1];
__device__ int   d_cur[N_NODES];
__device__ int   d_csr[N_EDGES];          // src ids grouped by dst
__device__ float d_score[N_NODES];
__device__ float d_gden[N_GRAPHS];
__device__ int   d_w64;                   // 1 if index tensors are int64

// index accessor: dtype-dispatched (int32 vs int64), clamped to valid range
__device__ __forceinline__ int load_idx(const void* p, long long i, int w64, int lim) {
    long long v = w64 ? ((const long long*)p)[i] : (long long)((const int*)p)[i];
    int r = (int)v;
    if (r < 0) r = 0;
    if (r >= lim) r = lim - 1;
    return r;
}

// ---------------- dtype detection ----------------
// If data is int64 with values < 2^32, every odd 32-bit word is 0.
// If data is int32 (random node ids), odd words are ~never all zero.
__global__ void detect_kernel(const unsigned int* __restrict__ raw) {
    __shared__ int nz;
    if (threadIdx.x == 0) nz = 0;
    __syncthreads();
    int cnt = 0;
    for (int i = threadIdx.x; i < 2048; i += 256) {
        if (raw[2 * i + 1] != 0u) cnt++;
    }
    atomicAdd(&nz, cnt);
    __syncthreads();
    if (threadIdx.x == 0) d_w64 = (nz < 16) ? 1 : 0;
}

// ---------------- init ----------------
__global__ void init_kernel(float* __restrict__ gout) {
    int i = blockIdx.x * blockDim.x + threadIdx.x;
    if (i < N_NODES) d_deg[i] = 0;
    if (i < N_GRAPHS) d_gden[i] = 0.f;
    if (i < N_GRAPHS * OUT_F) gout[i] = 0.f;
}

// ---------------- GEMM: h = x@W plus a_s/a_d head reductions ----------------
// 256 threads, tile = 64 nodes x 64 cols, thread tile 4x4.
// K=128 in two 64-wide stages; static smem ~33.3 KB.
__global__ void gemm_kernel(const float* __restrict__ x, const float* __restrict__ W,
                            const float* __restrict__ att_s, const float* __restrict__ att_d) {
    __shared__ __align__(16) float ws[64 * 64];   // W chunk [64 k][64 cols]
    __shared__ __align__(16) float xs[64 * 68];   // x tile [64 nodes][64 k + pad]
    const int tid = threadIdx.x;
    const int n0  = blockIdx.x * 64;

    const int ci = tid & 15;      // column group (4 cols each)
    const int ni = tid >> 4;      // node group  (4 nodes each)

    float acc[4][4];
#pragma unroll
    for (int j = 0; j < 4; j++)
#pragma unroll
        for (int q = 0; q < 4; q++) acc[j][q] = 0.f;

    for (int kk = 0; kk < 2; kk++) {
        const float4* W4 = (const float4*)W;
        float4* ws4 = (float4*)ws;
        for (int i = tid; i < 64 * 16; i += 256) ws4[i] = W4[kk * 1024 + i];

        for (int i = tid; i < 64 * 16; i += 256) {
            int nl = i >> 4;
            int kq = i & 15;
            float4 v = make_float4(0.f, 0.f, 0.f, 0.f);
            int n = n0 + nl;
            if (n < N_NODES) v = *(const float4*)(x + (size_t)n * IN_F + kk * 64 + kq * 4);
            *(float4*)(xs + nl * 68 + kq * 4) = v;
        }
        __syncthreads();

        const float* xbase = xs + (4 * ni) * 68;
        const float* wbase = ws + 4 * ci;
#pragma unroll 8
        for (int k = 0; k < 64; k++) {
            float4 wv = *(const float4*)(wbase + k * 64);
            float x0 = xbase[k];
            float x1 = xbase[68 + k];
            float x2 = xbase[136 + k];
            float x3 = xbase[204 + k];
            acc[0][0] += x0 * wv.x; acc[0][1] += x0 * wv.y; acc[0][2] += x0 * wv.z; acc[0][3] += x0 * wv.w;
            acc[1][0] += x1 * wv.x; acc[1][1] += x1 * wv.y; acc[1][2] += x1 * wv.z; acc[1][3] += x1 * wv.w;
            acc[2][0] += x2 * wv.x; acc[2][1] += x2 * wv.y; acc[2][2] += x2 * wv.z; acc[2][3] += x2 * wv.w;
            acc[3][0] += x3 * wv.x; acc[3][1] += x3 * wv.y; acc[3][2] += x3 * wv.z; acc[3][3] += x3 * wv.w;
        }
        __syncthreads();
    }

    float aw_s[4], aw_d[4];
#pragma unroll
    for (int q = 0; q < 4; q++) {
        aw_s[q] = att_s[4 * ci + q];
        aw_d[q] = att_d[4 * ci + q];
    }

#pragma unroll
    for (int j = 0; j < 4; j++) {
        int n = n0 + 4 * ni + j;
        float ps = 0.f, pd = 0.f;
#pragma unroll
        for (int q = 0; q < 4; q++) { ps += acc[j][q] * aw_s[q]; pd += acc[j][q] * aw_d[q]; }
        ps += __shfl_xor_sync(0xffffffffu, ps, 1);
        pd += __shfl_xor_sync(0xffffffffu, pd, 1);
        if (n < N_NODES) {
            float4 v = make_float4(acc[j][0], acc[j][1], acc[j][2], acc[j][3]);
            *(float4*)(d_h + (size_t)n * 64 + 4 * ci) = v;
            if ((ci & 1) == 0) {
                d_as[n * 8 + (ci >> 1)] = ps;
                d_ad[n * 8 + (ci >> 1)] = pd;
            }
        }
    }
}

// ---------------- CSR build ----------------
__global__ void hist_kernel(const void* __restrict__ ei) {
    int e = blockIdx.x * blockDim.x + threadIdx.x;
    int w64 = d_w64;
    if (e < N_EDGES) {
        int d = load_idx(ei, (long long)N_EDGES + e, w64, N_NODES);
        atomicAdd(&d_deg[d], 1);
    }
}

__global__ void scan_kernel() {
    __shared__ int wsum[32];
    __shared__ int chunk_total;
    __shared__ int s_running;
    int tid = threadIdx.x, lane = tid & 31, wid = tid >> 5;
    if (tid == 0) s_running = 0;
    __syncthreads();
    for (int base = 0; base < N_NODES; base += 1024) {
        int i = base + tid;
        int v = (i < N_NODES) ? d_deg[i] : 0;
        int inc = v;
#pragma unroll
        for (int o = 1; o < 32; o <<= 1) {
            int t = __shfl_up_sync(0xffffffffu, inc, o);
            if (lane >= o) inc += t;
        }
        if (lane == 31) wsum[wid] = inc;
        __syncthreads();
        if (wid == 0) {
            int s = wsum[lane];
            int si = s;
#pragma unroll
            for (int o = 1; o < 32; o <<= 1) {
                int t = __shfl_up_sync(0xffffffffu, si, o);
                if (lane >= o) si += t;
            }
            wsum[lane] = si - s;
            if (lane == 31) chunk_total = si;
        }
        __syncthreads();
        int excl = s_running + wsum[wid] + inc - v;
        if (i < N_NODES) { d_off[i] = excl; d_cur[i] = excl; }
        __syncthreads();
        if (tid == 0) s_running += chunk_total;
        __syncthreads();
    }
    if (tid == 0) d_off[N_NODES] = s_running;
}

__global__ void scatter_kernel(const void* __restrict__ ei) {
    int e = blockIdx.x * blockDim.x + threadIdx.x;
    int w64 = d_w64;
    if (e < N_EDGES) {
        int s = load_idx(ei, e, w64, N_NODES);
        int d = load_idx(ei, (long long)N_EDGES + e, w64, N_NODES);
        int p = atomicAdd(&d_cur[d], 1);
        d_csr[p] = s;
    }
}

// ---------------- GAT gather (warp per dst node, self-loop inline) ----------------
// Lane l owns channels {2l,2l+1} (head l>>2). Exp values computed in a
// (slot = l>>3, head = l&7) layout, 4 edges per chunk, broadcast via shfl.
// Edge softmax max-shift skipped (|e| small) — ratio identical to shifted form.
__global__ void gat_kernel(const float* __restrict__ bias, float* __restrict__ outp) {
    int w = (blockIdx.x * blockDim.x + threadIdx.x) >> 5;
    int l = threadIdx.x & 31;
    if (w >= N_NODES) return;
    const int d    = w;
    const int slot = l >> 3;
    const int hl   = l >> 2;
    const float adv = d_ad[d * 8 + (l & 7)];

    int beg = d_off[d];
    int ne  = d_off[d + 1] - beg;

    float2 acc = make_float2(0.f, 0.f);
    float den = 0.f;

    for (int base = 0; base <= ne; base += 4) {
        int cnt = ne + 1 - base; if (cnt > 4) cnt = 4;   // warp-uniform
        int eidx = base + slot;
        int src = 0;
        float ex = 0.f;
        if (slot < cnt) {
            src = (eidx < ne) ? d_csr[beg + eidx] : d;   // self loop last
            float e = d_as[src * 8 + (l & 7)] + adv;
            e = fmaxf(e, NEG_SLOPE * e);                 // leaky relu (slope<1)
            ex = __expf(e);
            den += ex;
        }
#pragma unroll 4
        for (int s = 0; s < cnt; s++) {
            int ssrc  = __shfl_sync(0xffffffffu, src, s * 8);
            float exc = __shfl_sync(0xffffffffu, ex,  s * 8 + hl);
            float2 hv = *(const float2*)(d_h + (size_t)ssrc * 64 + 2 * l);
            acc.x += hv.x * exc;
            acc.y += hv.y * exc;
        }
    }
    den += __shfl_xor_sync(0xffffffffu, den, 8);
    den += __shfl_xor_sync(0xffffffffu, den, 16);
    float denc = __shfl_sync(0xffffffffu, den, hl) + 1e-16f;

    float bx = bias[2 * l], by = bias[2 * l + 1];
    float2 o = make_float2(acc.x / denc + bx, acc.y / denc + by);
    *(float2*)(outp + (size_t)d * 64 + 2 * l) = o;
}

// ---------------- GraphConv aggr + pooling score (warp per dst, same CSR) ----------------
__global__ void aggr_kernel(const float* __restrict__ outp, const float* __restrict__ wrel,
                            const float* __restrict__ brel, const float* __restrict__ wroot) {
    int w = (blockIdx.x * blockDim.x + threadIdx.x) >> 5;
    int l = threadIdx.x & 31;
    if (w >= N_NODES) return;
    int d   = w;
    int beg = d_off[d], end = d_off[d + 1];
    float2 agg = make_float2(0.f, 0.f);
    int j = beg;
    for (; j + 4 <= end; j += 4) {
        int s0 = d_csr[j], s1 = d_csr[j + 1], s2 = d_csr[j + 2], s3 = d_csr[j + 3];
        float2 v0 = *(const float2*)(outp + (size_t)s0 * 64 + 2 * l);
        float2 v1 = *(const float2*)(outp + (size_t)s1 * 64 + 2 * l);
        float2 v2 = *(const float2*)(outp + (size_t)s2 * 64 + 2 * l);
        float2 v3 = *(const float2*)(outp + (size_t)s3 * 64 + 2 * l);
        agg.x += v0.x + v1.x + v2.x + v3.x;
        agg.y += v0.y + v1.y + v2.y + v3.y;
    }
    for (; j < end; j++) {
        int s0 = d_csr[j];
        float2 v0 = *(const float2*)(outp + (size_t)s0 * 64 + 2 * l);
        agg.x += v0.x; agg.y += v0.y;
    }
    float wrx = wrel[2 * l], wry = wrel[2 * l + 1];
    float wox = wroot[2 * l], woy = wroot[2 * l + 1];
    float2 od = *(const float2*)(outp + (size_t)d * 64 + 2 * l);
    float sc = agg.x * wrx + agg.y * wry + od.x * wox + od.y * woy;
#pragma unroll
    for (int o = 16; o; o >>= 1) sc += __shfl_xor_sync(0xffffffffu, sc, o);
    if (l == 0) d_score[d] = sc + brel[0];
}

// ---------------- per-graph softmax denom (no max shift; scores bounded) ----------------
__global__ void gden_kernel(const void* __restrict__ batch) {
    int n = blockIdx.x * blockDim.x + threadIdx.x;
    if (n >= N_NODES) return;
    int w64 = d_w64;
    int g = load_idx(batch, n, w64, N_GRAPHS);
    float ex = __expf(d_score[n]);
    d_score[n] = ex;                         // reuse as exp(score)
    atomicAdd(&d_gden[g], ex);
}

// ---------------- global add pool ----------------
__global__ void pool_kernel(const void* __restrict__ batch, const float* __restrict__ outp,
                            float* __restrict__ gout) {
    int i = blockIdx.x * blockDim.x + threadIdx.x;
    if (i >= N_NODES * 16) return;
    int n = i >> 4, q = i & 15;
    int w64 = d_w64;
    int g = load_idx(batch, n, w64, N_GRAPHS);
    float s = d_score[n] / (d_gden[g] + 1e-16f);
    float4 v = *(const float4*)(outp + (size_t)n * 64 + q * 4);
    float* gp = gout + g * 64 + q * 4;
    atomicAdd(gp + 0, v.x * s);
    atomicAdd(gp + 1, v.y * s);
    atomicAdd(gp + 2, v.z * s);
    atomicAdd(gp + 3, v.w * s);
}

// ---------------- launch ----------------
extern "C" void kernel_launch(void* const* d_in, const int* in_sizes, int n_in,
                              void* d_out, int out_size) {
    const float* x       = (const float*)d_in[0];
    const void*  ei      = d_in[1];
    const void*  batch   = d_in[2];
    const float* W       = (const float*)d_in[3];
    const float* att_src = (const float*)d_in[4];
    const float* att_dst = (const float*)d_in[5];
    const float* bias    = (const float*)d_in[6];
    const float* wrel    = (const float*)d_in[7];
    const float* brel    = (const float*)d_in[8];
    const float* wroot   = (const float*)d_in[9];
    (void)in_sizes; (void)n_in; (void)out_size;

    float* outp = (float*)d_out;
    float* gout = outp + (size_t)N_NODES * OUT_F;

    detect_kernel<<<1, 256>>>((const unsigned int*)ei);
    init_kernel<<<(N_NODES + 255) / 256, 256>>>(gout);
    gemm_kernel<<<(N_NODES + 63) / 64, 256>>>(x, W, att_src, att_dst);
    hist_kernel<<<(N_EDGES + 255) / 256, 256>>>(ei);
    scan_kernel<<<1, 1024>>>();
    scatter_kernel<<<(N_EDGES + 255) / 256, 256>>>(ei);
    gat_kernel<<<(N_NODES * 32 + 255) / 256, 256>>>(bias, outp);
    aggr_kernel<<<(N_NODES * 32 + 255) / 256, 256>>>(outp, wrel, brel, wroot);
    gden_kernel<<<(N_NODES + 255) / 256, 256>>>(batch);
    pool_kernel<<<(N_NODES * 16 + 255) / 256, 256>>>(batch, outp, gout);
}

// round 4
// speedup vs baseline: 1.2141x; 1.2141x over previous
#include <cuda_runtime.h>
#include <math.h>

#define N_NODES  50000
#define N_EDGES  800000
#define N_GRAPHS 512
#define IN_F     128
#define OUT_F    64
#define NEG_SLOPE 0.2f
#define NBLK     ((N_NODES + 255) / 256)   // 196 scan blocks

// ---------------- scratch (static device globals; no allocation) ----------------
__device__ float d_h [N_NODES * OUT_F];   // x @ W
__device__ float d_as[N_NODES * 8];       // per-node per-head src attention
__device__ float d_ad[N_NODES * 8];       // per-node per-head dst attention
__device__ int   d_deg[N_NODES];
__device__ int   d_off[N_NODES + 1];
__device__ int   d_cur[N_NODES];
__device__ int   d_csr[N_EDGES];          // src ids grouped by dst
__device__ int   d_src32[N_EDGES];
__device__ int   d_dst32[N_EDGES];
__device__ int   d_bsum[NBLK];
__device__ int   d_bpre[NBLK];
__device__ float d_score[N_NODES];
__device__ float d_gden[N_GRAPHS];
__device__ int   d_w64;                   // 1 if index tensors are int64

__device__ __forceinline__ int clampi(long long v, int lim) {
    int r = (int)v;
    if (r < 0) r = 0;
    if (r >= lim) r = lim - 1;
    return r;
}

// ---------------- dtype detection ----------------
// int64 node-ids < 2^32 -> odd 32-bit words all zero; int32 random ids -> not.
__global__ void detect_kernel(const unsigned int* __restrict__ raw) {
    __shared__ int nz;
    if (threadIdx.x == 0) nz = 0;
    __syncthreads();
    int cnt = 0;
    for (int i = threadIdx.x; i < 2048; i += 256)
        if (raw[2 * i + 1] != 0u) cnt++;
    atomicAdd(&nz, cnt);
    __syncthreads();
    if (threadIdx.x == 0) d_w64 = (nz < 16) ? 1 : 0;
}

// ---------------- init ----------------
__global__ void init_kernel(float* __restrict__ gout) {
    int i = blockIdx.x * blockDim.x + threadIdx.x;
    if (i < N_NODES) d_deg[i] = 0;
    if (i < N_GRAPHS) d_gden[i] = 0.f;
    if (i < N_GRAPHS * OUT_F) gout[i] = 0.f;
}

// ---------------- GEMM: h = x@W plus a_s/a_d head reductions ----------------
__global__ void gemm_kernel(const float* __restrict__ x, const float* __restrict__ W,
                            const float* __restrict__ att_s, const float* __restrict__ att_d) {
    __shared__ __align__(16) float ws[64 * 64];
    __shared__ __align__(16) float xs[64 * 68];
    const int tid = threadIdx.x;
    const int n0  = blockIdx.x * 64;
    const int ci = tid & 15;
    const int ni = tid >> 4;

    float acc[4][4];
#pragma unroll
    for (int j = 0; j < 4; j++)
#pragma unroll
        for (int q = 0; q < 4; q++) acc[j][q] = 0.f;

    for (int kk = 0; kk < 2; kk++) {
        const float4* W4 = (const float4*)W;
        float4* ws4 = (float4*)ws;
        for (int i = tid; i < 64 * 16; i += 256) ws4[i] = W4[kk * 1024 + i];
        for (int i = tid; i < 64 * 16; i += 256) {
            int nl = i >> 4, kq = i & 15;
            float4 v = make_float4(0.f, 0.f, 0.f, 0.f);
            int n = n0 + nl;
            if (n < N_NODES) v = *(const float4*)(x + (size_t)n * IN_F + kk * 64 + kq * 4);
            *(float4*)(xs + nl * 68 + kq * 4) = v;
        }
        __syncthreads();

        const float* xbase = xs + (4 * ni) * 68;
        const float* wbase = ws + 4 * ci;
#pragma unroll 8
        for (int k = 0; k < 64; k++) {
            float4 wv = *(const float4*)(wbase + k * 64);
            float x0 = xbase[k];
            float x1 = xbase[68 + k];
            float x2 = xbase[136 + k];
            float x3 = xbase[204 + k];
            acc[0][0] += x0 * wv.x; acc[0][1] += x0 * wv.y; acc[0][2] += x0 * wv.z; acc[0][3] += x0 * wv.w;
            acc[1][0] += x1 * wv.x; acc[1][1] += x1 * wv.y; acc[1][2] += x1 * wv.z; acc[1][3] += x1 * wv.w;
            acc[2][0] += x2 * wv.x; acc[2][1] += x2 * wv.y; acc[2][2] += x2 * wv.z; acc[2][3] += x2 * wv.w;
            acc[3][0] += x3 * wv.x; acc[3][1] += x3 * wv.y; acc[3][2] += x3 * wv.z; acc[3][3] += x3 * wv.w;
        }
        __syncthreads();
    }

    float aw_s[4], aw_d[4];
#pragma unroll
    for (int q = 0; q < 4; q++) { aw_s[q] = att_s[4 * ci + q]; aw_d[q] = att_d[4 * ci + q]; }

#pragma unroll
    for (int j = 0; j < 4; j++) {
        int n = n0 + 4 * ni + j;
        float ps = 0.f, pd = 0.f;
#pragma unroll
        for (int q = 0; q < 4; q++) { ps += acc[j][q] * aw_s[q]; pd += acc[j][q] * aw_d[q]; }
        ps += __shfl_xor_sync(0xffffffffu, ps, 1);
        pd += __shfl_xor_sync(0xffffffffu, pd, 1);
        if (n < N_NODES) {
            float4 v = make_float4(acc[j][0], acc[j][1], acc[j][2], acc[j][3]);
            *(float4*)(d_h + (size_t)n * 64 + 4 * ci) = v;
            if ((ci & 1) == 0) {
                d_as[n * 8 + (ci >> 1)] = ps;
                d_ad[n * 8 + (ci >> 1)] = pd;
            }
        }
    }
}

// ---------------- edge-index convert + histogram (2 edges/thread, 16B loads) ----------------
__global__ void conv_hist_kernel(const void* __restrict__ ei) {
    int t = blockIdx.x * blockDim.x + threadIdx.x;      // pair index
    if (2 * t >= N_EDGES) return;
    int w64 = d_w64;
    int s0, s1, dd0, dd1;
    if (w64) {
        const longlong2* p = (const longlong2*)ei;
        longlong2 sv = p[t];
        longlong2 dv = p[N_EDGES / 2 + t];
        s0 = clampi(sv.x, N_NODES); s1 = clampi(sv.y, N_NODES);
        dd0 = clampi(dv.x, N_NODES); dd1 = clampi(dv.y, N_NODES);
    } else {
        const int2* p = (const int2*)ei;
        int2 sv = p[t];
        int2 dv = p[N_EDGES / 2 + t];
        s0 = clampi(sv.x, N_NODES); s1 = clampi(sv.y, N_NODES);
        dd0 = clampi(dv.x, N_NODES); dd1 = clampi(dv.y, N_NODES);
    }
    *(int2*)(d_src32 + 2 * t) = make_int2(s0, s1);
    *(int2*)(d_dst32 + 2 * t) = make_int2(dd0, dd1);
    atomicAdd(&d_deg[dd0], 1);
    atomicAdd(&d_deg[dd1], 1);
}

// ---------------- multi-block exclusive scan of d_deg ----------------
__global__ void bsum_kernel() {
    __shared__ int wsum[8];
    int i = blockIdx.x * 256 + threadIdx.x;
    int lane = threadIdx.x & 31, wid = threadIdx.x >> 5;
    int v = (i < N_NODES) ? d_deg[i] : 0;
#pragma unroll
    for (int o = 16; o; o >>= 1) v += __shfl_xor_sync(0xffffffffu, v, o);
    if (lane == 0) wsum[wid] = v;
    __syncthreads();
    if (threadIdx.x == 0) {
        int s = 0;
#pragma unroll
        for (int q = 0; q < 8; q++) s += wsum[q];
        d_bsum[blockIdx.x] = s;
    }
}

__global__ void bscan_kernel() {
    __shared__ int wsum[8];
    int tid = threadIdx.x, lane = tid & 31, wid = tid >> 5;
    int v = (tid < NBLK) ? d_bsum[tid] : 0;
    int inc = v;
#pragma unroll
    for (int o = 1; o < 32; o <<= 1) {
        int t = __shfl_up_sync(0xffffffffu, inc, o);
        if (lane >= o) inc += t;
    }
    if (lane == 31) wsum[wid] = inc;
    __syncthreads();
    if (wid == 0 && lane < 8) {
        int s = wsum[lane];
        int si = s;
#pragma unroll
        for (int o = 1; o < 8; o <<= 1) {
            int t = __shfl_up_sync(0x000000ffu, si, o);
            if (lane >= o) si += t;
        }
        wsum[lane] = si - s;
    }
    __syncthreads();
    if (tid < NBLK) d_bpre[tid] = wsum[wid] + inc - v;   // exclusive prefix
}

__global__ void bapply_kernel() {
    __shared__ int wsum[8];
    int i = blockIdx.x * 256 + threadIdx.x;
    int lane = threadIdx.x & 31, wid = threadIdx.x >> 5;
    int v = (i < N_NODES) ? d_deg[i] : 0;
    int inc = v;
#pragma unroll
    for (int o = 1; o < 32; o <<= 1) {
        int t = __shfl_up_sync(0xffffffffu, inc, o);
        if (lane >= o) inc += t;
    }
    if (lane == 31) wsum[wid] = inc;
    __syncthreads();
    if (wid == 0 && lane < 8) {
        int s = wsum[lane];
        int si = s;
#pragma unroll
        for (int o = 1; o < 8; o <<= 1) {
            int t = __shfl_up_sync(0x000000ffu, si, o);
            if (lane >= o) si += t;
        }
        wsum[lane] = si - s;
    }
    __syncthreads();
    if (i < N_NODES) {
        int excl = d_bpre[blockIdx.x] + wsum[wid] + inc - v;
        d_off[i] = excl;
        d_cur[i] = excl;
    }
    if (i == 0) d_off[N_NODES] = N_EDGES;   // total is exact by construction
}

// ---------------- CSR scatter (int32 reads) ----------------
__global__ void scatter_kernel() {
    int e = blockIdx.x * blockDim.x + threadIdx.x;
    if (e < N_EDGES) {
        int s = d_src32[e];
        int d = d_dst32[e];
        int p = atomicAdd(&d_cur[d], 1);
        d_csr[p] = s;
    }
}

// ---------------- GAT gather (warp per dst node, self-loop inline) ----------------
__global__ void gat_kernel(const float* __restrict__ bias, float* __restrict__ outp) {
    int w = (blockIdx.x * blockDim.x + threadIdx.x) >> 5;
    int l = threadIdx.x & 31;
    if (w >= N_NODES) return;
    const int d    = w;
    const int slot = l >> 3;
    const int hl   = l >> 2;
    const float adv = d_ad[d * 8 + (l & 7)];

    int beg = d_off[d];
    int ne  = d_off[d + 1] - beg;

    float2 acc = make_float2(0.f, 0.f);
    float den = 0.f;

    for (int base = 0; base <= ne; base += 4) {
        int cnt = ne + 1 - base; if (cnt > 4) cnt = 4;   // warp-uniform
        int eidx = base + slot;
        int src = 0;
        float ex = 0.f;
        if (slot < cnt) {
            src = (eidx < ne) ? d_csr[beg + eidx] : d;   // self loop last
            float e = d_as[src * 8 + (l & 7)] + adv;
            e = fmaxf(e, NEG_SLOPE * e);                 // leaky relu (slope<1)
            ex = __expf(e);
            den += ex;
        }
#pragma unroll 4
        for (int s = 0; s < cnt; s++) {
            int ssrc  = __shfl_sync(0xffffffffu, src, s * 8);
            float exc = __shfl_sync(0xffffffffu, ex,  s * 8 + hl);
            float2 hv = *(const float2*)(d_h + (size_t)ssrc * 64 + 2 * l);
            acc.x += hv.x * exc;
            acc.y += hv.y * exc;
        }
    }
    den += __shfl_xor_sync(0xffffffffu, den, 8);
    den += __shfl_xor_sync(0xffffffffu, den, 16);
    float denc = __shfl_sync(0xffffffffu, den, hl) + 1e-16f;

    float bx = bias[2 * l], by = bias[2 * l + 1];
    float2 o = make_float2(acc.x / denc + bx, acc.y / denc + by);
    *(float2*)(outp + (size_t)d * 64 + 2 * l) = o;
}

// ---------------- GraphConv aggr + score + per-graph softmax denom (fused) ----------------
__global__ void aggr_kernel(const float* __restrict__ outp, const float* __restrict__ wrel,
                            const float* __restrict__ brel, const float* __restrict__ wroot,
                            const void* __restrict__ batch) {
    int w = (blockIdx.x * blockDim.x + threadIdx.x) >> 5;
    int l = threadIdx.x & 31;
    if (w >= N_NODES) return;
    int d   = w;
    int beg = d_off[d], end = d_off[d + 1];
    float2 agg = make_float2(0.f, 0.f);
    int j = beg;
    for (; j + 4 <= end; j += 4) {
        int s0 = d_csr[j], s1 = d_csr[j + 1], s2 = d_csr[j + 2], s3 = d_csr[j + 3];
        float2 v0 = *(const float2*)(outp + (size_t)s0 * 64 + 2 * l);
        float2 v1 = *(const float2*)(outp + (size_t)s1 * 64 + 2 * l);
        float2 v2 = *(const float2*)(outp + (size_t)s2 * 64 + 2 * l);
        float2 v3 = *(const float2*)(outp + (size_t)s3 * 64 + 2 * l);
        agg.x += v0.x + v1.x + v2.x + v3.x;
        agg.y += v0.y + v1.y + v2.y + v3.y;
    }
    for (; j < end; j++) {
        int s0 = d_csr[j];
        float2 v0 = *(const float2*)(outp + (size_t)s0 * 64 + 2 * l);
        agg.x += v0.x; agg.y += v0.y;
    }
    float wrx = wrel[2 * l], wry = wrel[2 * l + 1];
    float wox = wroot[2 * l], woy = wroot[2 * l + 1];
    float2 od = *(const float2*)(outp + (size_t)d * 64 + 2 * l);
    float sc = agg.x * wrx + agg.y * wry + od.x * wox + od.y * woy;
#pragma unroll
    for (int o = 16; o; o >>= 1) sc += __shfl_xor_sync(0xffffffffu, sc, o);
    if (l == 0) {
        // per-graph softmax without max-shift (scores bounded small by weight scale)
        float ex = __expf(sc + brel[0]);
        d_score[d] = ex;
        int w64 = d_w64;
        long long bv = w64 ? ((const long long*)batch)[d] : (long long)((const int*)batch)[d];
        int g = clampi(bv, N_GRAPHS);
        atomicAdd(&d_gden[g], ex);
    }
}

// ---------------- global add pool ----------------
__global__ void pool_kernel(const void* __restrict__ batch, const float* __restrict__ outp,
                            float* __restrict__ gout) {
    int i = blockIdx.x * blockDim.x + threadIdx.x;
    if (i >= N_NODES * 16) return;
    int n = i >> 4, q = i & 15;
    int w64 = d_w64;
    long long bv = w64 ? ((const long long*)batch)[n] : (long long)((const int*)batch)[n];
    int g = clampi(bv, N_GRAPHS);
    float s = d_score[n] / (d_gden[g] + 1e-16f);
    float4 v = *(const float4*)(outp + (size_t)n * 64 + q * 4);
    float* gp = gout + g * 64 + q * 4;
    atomicAdd(gp + 0, v.x * s);
    atomicAdd(gp + 1, v.y * s);
    atomicAdd(gp + 2, v.z * s);
    atomicAdd(gp + 3, v.w * s);
}

// ---------------- launch ----------------
extern "C" void kernel_launch(void* const* d_in, const int* in_sizes, int n_in,
                              void* d_out, int out_size) {
    const float* x       = (const float*)d_in[0];
    const void*  ei      = d_in[1];
    const void*  batch   = d_in[2];
    const float* W       = (const float*)d_in[3];
    const float* att_src = (const float*)d_in[4];
    const float* att_dst = (const float*)d_in[5];
    const float* bias    = (const float*)d_in[6];
    const float* wrel    = (const float*)d_in[7];
    const float* brel    = (const float*)d_in[8];
    const float* wroot   = (const float*)d_in[9];
    (void)in_sizes; (void)n_in; (void)out_size;

    float* outp = (float*)d_out;
    float* gout = outp + (size_t)N_NODES * OUT_F;

    detect_kernel<<<1, 256>>>((const unsigned int*)ei);
    init_kernel<<<(N_NODES + 255) / 256, 256>>>(gout);
    gemm_kernel<<<(N_NODES + 63) / 64, 256>>>(x, W, att_src, att_dst);
    conv_hist_kernel<<<(N_EDGES / 2 + 255) / 256, 256>>>(ei);
    bsum_kernel<<<NBLK, 256>>>();
    bscan_kernel<<<1, 256>>>();
    bapply_kernel<<<NBLK, 256>>>();
    scatter_kernel<<<(N_EDGES + 255) / 256, 256>>>();
    gat_kernel<<<(N_NODES * 32 + 255) / 256, 256>>>(bias, outp);
    aggr_kernel<<<(N_NODES * 32 + 255) / 256, 256>>>(outp, wrel, brel, wroot, batch);
    pool_kernel<<<(N_NODES * 16 + 255) / 256, 256>>>(batch, outp, gout);
}

// round 5
// speedup vs baseline: 1.2649x; 1.0419x over previous
#include <cuda_runtime.h>
#include <math.h>

#define N_NODES  50000
#define N_EDGES  800000
#define N_GRAPHS 512
#define IN_F     128
#define OUT_F    64
#define NEG_SLOPE 0.2f
#define NBLK     ((N_NODES + 255) / 256)   // 196 scan blocks

// ---------------- scratch (static device globals; no allocation) ----------------
__device__ float d_h [N_NODES * OUT_F];   // x @ W
__device__ float d_as[N_NODES * 8];       // per-node per-head src attention
__device__ float d_ad[N_NODES * 8];       // per-node per-head dst attention
__device__ int   d_deg[N_NODES];
__device__ int   d_off[N_NODES + 1];
__device__ int   d_cur[N_NODES];
__device__ int   d_csr[N_EDGES];          // src ids grouped by dst
__device__ int   d_src32[N_EDGES];
__device__ int   d_dst32[N_EDGES];
__device__ int   d_bsum[NBLK];
__device__ int   d_bpre[NBLK];
__device__ float d_prel [N_NODES];        // out[n] . w_rel
__device__ float d_sroot[N_NODES];        // out[n] . w_root
__device__ float d_score[N_NODES];        // exp(pool score)
__device__ float d_gden[N_GRAPHS];
__device__ int   d_w64;                   // 1 if index tensors are int64

__device__ __forceinline__ int clampi(long long v, int lim) {
    int r = (int)v;
    if (r < 0) r = 0;
    if (r >= lim) r = lim - 1;
    return r;
}

// ---------------- dtype detection ----------------
// int64 node-ids < 2^32 -> odd 32-bit words all zero; int32 random ids -> not.
__global__ void detect_kernel(const unsigned int* __restrict__ raw) {
    __shared__ int nz;
    if (threadIdx.x == 0) nz = 0;
    __syncthreads();
    int cnt = 0;
    for (int i = threadIdx.x; i < 2048; i += 256)
        if (raw[2 * i + 1] != 0u) cnt++;
    atomicAdd(&nz, cnt);
    __syncthreads();
    if (threadIdx.x == 0) d_w64 = (nz < 16) ? 1 : 0;
}

// ---------------- init ----------------
__global__ void init_kernel(float* __restrict__ gout) {
    int i = blockIdx.x * blockDim.x + threadIdx.x;
    if (i < N_NODES) d_deg[i] = 0;
    if (i < N_GRAPHS) d_gden[i] = 0.f;
    if (i < N_GRAPHS * OUT_F) gout[i] = 0.f;
}

// ---------------- GEMM: h = x@W plus a_s/a_d head reductions ----------------
__global__ void gemm_kernel(const float* __restrict__ x, const float* __restrict__ W,
                            const float* __restrict__ att_s, const float* __restrict__ att_d) {
    __shared__ __align__(16) float ws[64 * 64];
    __shared__ __align__(16) float xs[64 * 68];
    const int tid = threadIdx.x;
    const int n0  = blockIdx.x * 64;
    const int ci = tid & 15;
    const int ni = tid >> 4;

    float acc[4][4];
#pragma unroll
    for (int j = 0; j < 4; j++)
#pragma unroll
        for (int q = 0; q < 4; q++) acc[j][q] = 0.f;

    for (int kk = 0; kk < 2; kk++) {
        const float4* W4 = (const float4*)W;
        float4* ws4 = (float4*)ws;
        for (int i = tid; i < 64 * 16; i += 256) ws4[i] = W4[kk * 1024 + i];
        for (int i = tid; i < 64 * 16; i += 256) {
            int nl = i >> 4, kq = i & 15;
            float4 v = make_float4(0.f, 0.f, 0.f, 0.f);
            int n = n0 + nl;
            if (n < N_NODES) v = *(const float4*)(x + (size_t)n * IN_F + kk * 64 + kq * 4);
            *(float4*)(xs + nl * 68 + kq * 4) = v;
        }
        __syncthreads();

        const float* xbase = xs + (4 * ni) * 68;
        const float* wbase = ws + 4 * ci;
#pragma unroll 8
        for (int k = 0; k < 64; k++) {
            float4 wv = *(const float4*)(wbase + k * 64);
            float x0 = xbase[k];
            float x1 = xbase[68 + k];
            float x2 = xbase[136 + k];
            float x3 = xbase[204 + k];
            acc[0][0] += x0 * wv.x; acc[0][1] += x0 * wv.y; acc[0][2] += x0 * wv.z; acc[0][3] += x0 * wv.w;
            acc[1][0] += x1 * wv.x; acc[1][1] += x1 * wv.y; acc[1][2] += x1 * wv.z; acc[1][3] += x1 * wv.w;
            acc[2][0] += x2 * wv.x; acc[2][1] += x2 * wv.y; acc[2][2] += x2 * wv.z; acc[2][3] += x2 * wv.w;
            acc[3][0] += x3 * wv.x; acc[3][1] += x3 * wv.y; acc[3][2] += x3 * wv.z; acc[3][3] += x3 * wv.w;
        }
        __syncthreads();
    }

    float aw_s[4], aw_d[4];
#pragma unroll
    for (int q = 0; q < 4; q++) { aw_s[q] = att_s[4 * ci + q]; aw_d[q] = att_d[4 * ci + q]; }

#pragma unroll
    for (int j = 0; j < 4; j++) {
        int n = n0 + 4 * ni + j;
        float ps = 0.f, pd = 0.f;
#pragma unroll
        for (int q = 0; q < 4; q++) { ps += acc[j][q] * aw_s[q]; pd += acc[j][q] * aw_d[q]; }
        ps += __shfl_xor_sync(0xffffffffu, ps, 1);
        pd += __shfl_xor_sync(0xffffffffu, pd, 1);
        if (n < N_NODES) {
            float4 v = make_float4(acc[j][0], acc[j][1], acc[j][2], acc[j][3]);
            *(float4*)(d_h + (size_t)n * 64 + 4 * ci) = v;
            if ((ci & 1) == 0) {
                d_as[n * 8 + (ci >> 1)] = ps;
                d_ad[n * 8 + (ci >> 1)] = pd;
            }
        }
    }
}

// ---------------- edge-index convert + histogram (4 edges/thread) ----------------
__global__ void conv_hist_kernel(const void* __restrict__ ei) {
    int t = blockIdx.x * blockDim.x + threadIdx.x;      // quad index
    if (4 * t >= N_EDGES) return;
    int w64 = d_w64;
    int s[4], dd[4];
    if (w64) {
        const longlong2* p = (const longlong2*)ei;
        longlong2 sv0 = p[2 * t], sv1 = p[2 * t + 1];
        longlong2 dv0 = p[N_EDGES / 2 + 2 * t], dv1 = p[N_EDGES / 2 + 2 * t + 1];
        s[0] = clampi(sv0.x, N_NODES); s[1] = clampi(sv0.y, N_NODES);
        s[2] = clampi(sv1.x, N_NODES); s[3] = clampi(sv1.y, N_NODES);
        dd[0] = clampi(dv0.x, N_NODES); dd[1] = clampi(dv0.y, N_NODES);
        dd[2] = clampi(dv1.x, N_NODES); dd[3] = clampi(dv1.y, N_NODES);
    } else {
        const int4* p = (const int4*)ei;
        int4 sv = p[t];
        int4 dv = p[N_EDGES / 4 + t];
        s[0] = clampi(sv.x, N_NODES); s[1] = clampi(sv.y, N_NODES);
        s[2] = clampi(sv.z, N_NODES); s[3] = clampi(sv.w, N_NODES);
        dd[0] = clampi(dv.x, N_NODES); dd[1] = clampi(dv.y, N_NODES);
        dd[2] = clampi(dv.z, N_NODES); dd[3] = clampi(dv.w, N_NODES);
    }
    *(int4*)(d_src32 + 4 * t) = make_int4(s[0], s[1], s[2], s[3]);
    *(int4*)(d_dst32 + 4 * t) = make_int4(dd[0], dd[1], dd[2], dd[3]);
#pragma unroll
    for (int q = 0; q < 4; q++) atomicAdd(&d_deg[dd[q]], 1);
}

// ---------------- multi-block exclusive scan of d_deg ----------------
__global__ void bsum_kernel() {
    __shared__ int wsum[8];
    int i = blockIdx.x * 256 + threadIdx.x;
    int lane = threadIdx.x & 31, wid = threadIdx.x >> 5;
    int v = (i < N_NODES) ? d_deg[i] : 0;
#pragma unroll
    for (int o = 16; o; o >>= 1) v += __shfl_xor_sync(0xffffffffu, v, o);
    if (lane == 0) wsum[wid] = v;
    __syncthreads();
    if (threadIdx.x == 0) {
        int sacc = 0;
#pragma unroll
        for (int q = 0; q < 8; q++) sacc += wsum[q];
        d_bsum[blockIdx.x] = sacc;
    }
}

__global__ void bscan_kernel() {
    __shared__ int wsum[8];
    int tid = threadIdx.x, lane = tid & 31, wid = tid >> 5;
    int v = (tid < NBLK) ? d_bsum[tid] : 0;
    int inc = v;
#pragma unroll
    for (int o = 1; o < 32; o <<= 1) {
        int t = __shfl_up_sync(0xffffffffu, inc, o);
        if (lane >= o) inc += t;
    }
    if (lane == 31) wsum[wid] = inc;
    __syncthreads();
    if (wid == 0 && lane < 8) {
        int sv = wsum[lane];
        int si = sv;
#pragma unroll
        for (int o = 1; o < 8; o <<= 1) {
            int t = __shfl_up_sync(0x000000ffu, si, o);
            if (lane >= o) si += t;
        }
        wsum[lane] = si - sv;
    }
    __syncthreads();
    if (tid < NBLK) d_bpre[tid] = wsum[wid] + inc - v;   // exclusive prefix
}

__global__ void bapply_kernel() {
    __shared__ int wsum[8];
    int i = blockIdx.x * 256 + threadIdx.x;
    int lane = threadIdx.x & 31, wid = threadIdx.x >> 5;
    int v = (i < N_NODES) ? d_deg[i] : 0;
    int inc = v;
#pragma unroll
    for (int o = 1; o < 32; o <<= 1) {
        int t = __shfl_up_sync(0xffffffffu, inc, o);
        if (lane >= o) inc += t;
    }
    if (lane == 31) wsum[wid] = inc;
    __syncthreads();
    if (wid == 0 && lane < 8) {
        int sv = wsum[lane];
        int si = sv;
#pragma unroll
        for (int o = 1; o < 8; o <<= 1) {
            int t = __shfl_up_sync(0x000000ffu, si, o);
            if (lane >= o) si += t;
        }
        wsum[lane] = si - sv;
    }
    __syncthreads();
    if (i < N_NODES) {
        int excl = d_bpre[blockIdx.x] + wsum[wid] + inc - v;
        d_off[i] = excl;
        d_cur[i] = excl;
    }
    if (i == 0) d_off[N_NODES] = N_EDGES;
}

// ---------------- CSR scatter (int32 reads, 2 edges/thread) ----------------
__global__ void scatter_kernel() {
    int t = blockIdx.x * blockDim.x + threadIdx.x;
    if (2 * t >= N_EDGES) return;
    int2 sv = *(const int2*)(d_src32 + 2 * t);
    int2 dv = *(const int2*)(d_dst32 + 2 * t);
    int p0 = atomicAdd(&d_cur[dv.x], 1);
    int p1 = atomicAdd(&d_cur[dv.y], 1);
    d_csr[p0] = sv.x;
    d_csr[p1] = sv.y;
}

// ---------------- GAT gather (warp per dst node, self-loop inline) ----------------
// Epilogue also emits the two pooling dot products (out.w_rel, out.w_root),
// exploiting linearity so aggr_kernel gathers 4 B/edge instead of 256 B/edge.
__global__ void gat_kernel(const float* __restrict__ bias, float* __restrict__ outp,
                           const float* __restrict__ wrel, const float* __restrict__ wroot) {
    int w = (blockIdx.x * blockDim.x + threadIdx.x) >> 5;
    int l = threadIdx.x & 31;
    if (w >= N_NODES) return;
    const int d    = w;
    const int slot = l >> 3;
    const int hl   = l >> 2;
    const float adv = d_ad[d * 8 + (l & 7)];

    int beg = d_off[d];
    int ne  = d_off[d + 1] - beg;

    float2 acc = make_float2(0.f, 0.f);
    float den = 0.f;

    for (int base = 0; base <= ne; base += 4) {
        int cnt = ne + 1 - base; if (cnt > 4) cnt = 4;   // warp-uniform
        int eidx = base + slot;
        int src = 0;
        float ex = 0.f;
        if (slot < cnt) {
            src = (eidx < ne) ? d_csr[beg + eidx] : d;   // self loop last
            float e = d_as[src * 8 + (l & 7)] + adv;
            e = fmaxf(e, NEG_SLOPE * e);                 // leaky relu (slope<1)
            ex = __expf(e);
            den += ex;
        }
#pragma unroll 4
        for (int s = 0; s < cnt; s++) {
            int ssrc  = __shfl_sync(0xffffffffu, src, s * 8);
            float exc = __shfl_sync(0xffffffffu, ex,  s * 8 + hl);
            float2 hv = *(const float2*)(d_h + (size_t)ssrc * 64 + 2 * l);
            acc.x += hv.x * exc;
            acc.y += hv.y * exc;
        }
    }
    den += __shfl_xor_sync(0xffffffffu, den, 8);
    den += __shfl_xor_sync(0xffffffffu, den, 16);
    float denc = __shfl_sync(0xffffffffu, den, hl) + 1e-16f;

    float bx = bias[2 * l], by = bias[2 * l + 1];
    float2 o = make_float2(acc.x / denc + bx, acc.y / denc + by);
    *(float2*)(outp + (size_t)d * 64 + 2 * l) = o;

    // pooling dot products (linearity trick)
    float wrx = wrel[2 * l],  wry = wrel[2 * l + 1];
    float wox = wroot[2 * l], woy = wroot[2 * l + 1];
    float pr = o.x * wrx + o.y * wry;
    float po = o.x * wox + o.y * woy;
#pragma unroll
    for (int off = 16; off; off >>= 1) {
        pr += __shfl_xor_sync(0xffffffffu, pr, off);
        po += __shfl_xor_sync(0xffffffffu, po, off);
    }
    if (l == 0) { d_prel[d] = pr; d_sroot[d] = po; }
}

// ---------------- pooling score: scalar gather + exp + per-graph denom ----------------
__global__ void score_kernel(const float* __restrict__ brel, const void* __restrict__ batch) {
    int w = (blockIdx.x * blockDim.x + threadIdx.x) >> 5;
    int l = threadIdx.x & 31;
    if (w >= N_NODES) return;
    int d   = w;
    int beg = d_off[d], end = d_off[d + 1];
    float sum = 0.f;
    for (int j = beg + l; j < end; j += 32)
        sum += d_prel[d_csr[j]];
#pragma unroll
    for (int o = 16; o; o >>= 1) sum += __shfl_xor_sync(0xffffffffu, sum, o);
    if (l == 0) {
        float ex = __expf(sum + d_sroot[d] + brel[0]);   // no max-shift: scores bounded
        d_score[d] = ex;
        int w64 = d_w64;
        long long bv = w64 ? ((const long long*)batch)[d] : (long long)((const int*)batch)[d];
        int g = clampi(bv, N_GRAPHS);
        atomicAdd(&d_gden[g], ex);
    }
}

// ---------------- global add pool ----------------
__global__ void pool_kernel(const void* __restrict__ batch, const float* __restrict__ outp,
                            float* __restrict__ gout) {
    int i = blockIdx.x * blockDim.x + threadIdx.x;
    if (i >= N_NODES * 16) return;
    int n = i >> 4, q = i & 15;
    int w64 = d_w64;
    long long bv = w64 ? ((const long long*)batch)[n] : (long long)((const int*)batch)[n];
    int g = clampi(bv, N_GRAPHS);
    float s = d_score[n] / (d_gden[g] + 1e-16f);
    float4 v = *(const float4*)(outp + (size_t)n * 64 + q * 4);
    float* gp = gout + g * 64 + q * 4;
    atomicAdd(gp + 0, v.x * s);
    atomicAdd(gp + 1, v.y * s);
    atomicAdd(gp + 2, v.z * s);
    atomicAdd(gp + 3, v.w * s);
}

// ---------------- launch ----------------
extern "C" void kernel_launch(void* const* d_in, const int* in_sizes, int n_in,
                              void* d_out, int out_size) {
    const float* x       = (const float*)d_in[0];
    const void*  ei      = d_in[1];
    const void*  batch   = d_in[2];
    const float* W       = (const float*)d_in[3];
    const float* att_src = (const float*)d_in[4];
    const float* att_dst = (const float*)d_in[5];
    const float* bias    = (const float*)d_in[6];
    const float* wrel    = (const float*)d_in[7];
    const float* brel    = (const float*)d_in[8];
    const float* wroot   = (const float*)d_in[9];
    (void)in_sizes; (void)n_in; (void)out_size;

    float* outp = (float*)d_out;
    float* gout = outp + (size_t)N_NODES * OUT_F;

    detect_kernel<<<1, 256>>>((const unsigned int*)ei);
    init_kernel<<<(N_NODES + 255) / 256, 256>>>(gout);
    gemm_kernel<<<(N_NODES + 63) / 64, 256>>>(x, W, att_src, att_dst);
    conv_hist_kernel<<<(N_EDGES / 4 + 255) / 256, 256>>>(ei);
    bsum_kernel<<<NBLK, 256>>>();
    bscan_kernel<<<1, 256>>>();
    bapply_kernel<<<NBLK, 256>>>();
    scatter_kernel<<<(N_EDGES / 2 + 255) / 256, 256>>>();
    gat_kernel<<<(N_NODES * 32 + 255) / 256, 256>>>(bias, outp, wrel, wroot);
    score_kernel<<<(N_NODES * 32 + 255) / 256, 256>>>(brel, batch);
    pool_kernel<<<(N_NODES * 16 + 255) / 256, 256>>>(batch, outp, gout);
}

// round 6
// speedup vs baseline: 1.4835x; 1.1728x over previous
#include <cuda_runtime.h>
#include <math.h>

#define N_NODES  50000
#define N_EDGES  800000
#define N_GRAPHS 512
#define IN_F     128
#define OUT_F    64
#define NEG_SLOPE 0.2f
#define NBLK     ((N_NODES + 255) / 256)   // 196 scan blocks

// ---------------- scratch (static device globals; no allocation) ----------------
__device__ float d_h [N_NODES * OUT_F];   // x @ W
__device__ float d_as[N_NODES * 8];       // per-node per-head src attention
__device__ float d_ad[N_NODES * 8];       // per-node per-head dst attention
__device__ int   d_deg[N_NODES];
__device__ int   d_off[N_NODES + 1];
__device__ int   d_cur[N_NODES];
__device__ int   d_csr[N_EDGES];          // src ids grouped by dst
__device__ int   d_src32[N_EDGES];
__device__ int   d_dst32[N_EDGES];
__device__ int   d_bsum[NBLK];
__device__ float d_prel [N_NODES];        // out[n] . w_rel
__device__ float d_sroot[N_NODES];        // out[n] . w_root
__device__ float d_score[N_NODES];        // exp(pool score)
__device__ float d_gden[N_GRAPHS];
__device__ int   d_w64;                   // 1 if index tensors are int64

__device__ __forceinline__ int clampi(long long v, int lim) {
    int r = (int)v;
    if (r < 0) r = 0;
    if (r >= lim) r = lim - 1;
    return r;
}

// ---------------- setup: init scratch + dtype detect (block 0) ----------------
// int64 node-ids < 2^32 -> odd 32-bit words all zero; int32 random ids -> not.
__global__ void setup_kernel(const unsigned int* __restrict__ raw, float* __restrict__ gout) {
    int i = blockIdx.x * 256 + threadIdx.x;
    if (i < N_NODES) d_deg[i] = 0;
    if (i < N_GRAPHS) d_gden[i] = 0.f;
    if (i < N_GRAPHS * OUT_F) gout[i] = 0.f;
    if (blockIdx.x == 0) {
        __shared__ int nz;
        if (threadIdx.x == 0) nz = 0;
        __syncthreads();
        int cnt = 0;
        for (int k = threadIdx.x; k < 2048; k += 256)
            if (raw[2 * k + 1] != 0u) cnt++;
        if (cnt) atomicAdd(&nz, cnt);
        __syncthreads();
        if (threadIdx.x == 0) d_w64 = (nz < 16) ? 1 : 0;
    }
}

// ---------------- GEMM: h = x@W plus a_s/a_d head reductions (FMA floor) ----------------
__global__ void gemm_kernel(const float* __restrict__ x, const float* __restrict__ W,
                            const float* __restrict__ att_s, const float* __restrict__ att_d) {
    __shared__ __align__(16) float ws[64 * 64];
    __shared__ __align__(16) float xs[64 * 68];
    const int tid = threadIdx.x;
    const int n0  = blockIdx.x * 64;
    const int ci = tid & 15;
    const int ni = tid >> 4;

    float acc[4][4];
#pragma unroll
    for (int j = 0; j < 4; j++)
#pragma unroll
        for (int q = 0; q < 4; q++) acc[j][q] = 0.f;

    for (int kk = 0; kk < 2; kk++) {
        const float4* W4 = (const float4*)W;
        float4* ws4 = (float4*)ws;
        for (int i = tid; i < 64 * 16; i += 256) ws4[i] = W4[kk * 1024 + i];
        for (int i = tid; i < 64 * 16; i += 256) {
            int nl = i >> 4, kq = i & 15;
            float4 v = make_float4(0.f, 0.f, 0.f, 0.f);
            int n = n0 + nl;
            if (n < N_NODES) v = *(const float4*)(x + (size_t)n * IN_F + kk * 64 + kq * 4);
            *(float4*)(xs + nl * 68 + kq * 4) = v;
        }
        __syncthreads();

        const float* xbase = xs + (4 * ni) * 68;
        const float* wbase = ws + 4 * ci;
#pragma unroll 8
        for (int k = 0; k < 64; k++) {
            float4 wv = *(const float4*)(wbase + k * 64);
            float x0 = xbase[k];
            float x1 = xbase[68 + k];
            float x2 = xbase[136 + k];
            float x3 = xbase[204 + k];
            acc[0][0] += x0 * wv.x; acc[0][1] += x0 * wv.y; acc[0][2] += x0 * wv.z; acc[0][3] += x0 * wv.w;
            acc[1][0] += x1 * wv.x; acc[1][1] += x1 * wv.y; acc[1][2] += x1 * wv.z; acc[1][3] += x1 * wv.w;
            acc[2][0] += x2 * wv.x; acc[2][1] += x2 * wv.y; acc[2][2] += x2 * wv.z; acc[2][3] += x2 * wv.w;
            acc[3][0] += x3 * wv.x; acc[3][1] += x3 * wv.y; acc[3][2] += x3 * wv.z; acc[3][3] += x3 * wv.w;
        }
        __syncthreads();
    }

    float aw_s[4], aw_d[4];
#pragma unroll
    for (int q = 0; q < 4; q++) { aw_s[q] = att_s[4 * ci + q]; aw_d[q] = att_d[4 * ci + q]; }

#pragma unroll
    for (int j = 0; j < 4; j++) {
        int n = n0 + 4 * ni + j;
        float ps = 0.f, pd = 0.f;
#pragma unroll
        for (int q = 0; q < 4; q++) { ps += acc[j][q] * aw_s[q]; pd += acc[j][q] * aw_d[q]; }
        ps += __shfl_xor_sync(0xffffffffu, ps, 1);
        pd += __shfl_xor_sync(0xffffffffu, pd, 1);
        if (n < N_NODES) {
            float4 v = make_float4(acc[j][0], acc[j][1], acc[j][2], acc[j][3]);
            *(float4*)(d_h + (size_t)n * 64 + 4 * ci) = v;
            if ((ci & 1) == 0) {
                d_as[n * 8 + (ci >> 1)] = ps;
                d_ad[n * 8 + (ci >> 1)] = pd;
            }
        }
    }
}

// ---------------- edge-index convert + histogram (4 edges/thread) ----------------
__global__ void conv_hist_kernel(const void* __restrict__ ei) {
    int t = blockIdx.x * blockDim.x + threadIdx.x;      // quad index
    if (4 * t >= N_EDGES) return;
    int w64 = d_w64;
    int s[4], dd[4];
    if (w64) {
        const longlong2* p = (const longlong2*)ei;
        longlong2 sv0 = p[2 * t], sv1 = p[2 * t + 1];
        longlong2 dv0 = p[N_EDGES / 2 + 2 * t], dv1 = p[N_EDGES / 2 + 2 * t + 1];
        s[0] = clampi(sv0.x, N_NODES); s[1] = clampi(sv0.y, N_NODES);
        s[2] = clampi(sv1.x, N_NODES); s[3] = clampi(sv1.y, N_NODES);
        dd[0] = clampi(dv0.x, N_NODES); dd[1] = clampi(dv0.y, N_NODES);
        dd[2] = clampi(dv1.x, N_NODES); dd[3] = clampi(dv1.y, N_NODES);
    } else {
        const int4* p = (const int4*)ei;
        int4 sv = p[t];
        int4 dv = p[N_EDGES / 4 + t];
        s[0] = clampi(sv.x, N_NODES); s[1] = clampi(sv.y, N_NODES);
        s[2] = clampi(sv.z, N_NODES); s[3] = clampi(sv.w, N_NODES);
        dd[0] = clampi(dv.x, N_NODES); dd[1] = clampi(dv.y, N_NODES);
        dd[2] = clampi(dv.z, N_NODES); dd[3] = clampi(dv.w, N_NODES);
    }
    *(int4*)(d_src32 + 4 * t) = make_int4(s[0], s[1], s[2], s[3]);
    *(int4*)(d_dst32 + 4 * t) = make_int4(dd[0], dd[1], dd[2], dd[3]);
#pragma unroll
    for (int q = 0; q < 4; q++) atomicAdd(&d_deg[dd[q]], 1);
}

// ---------------- block partial sums of d_deg ----------------
__global__ void bsum_kernel() {
    __shared__ int wsum[8];
    int i = blockIdx.x * 256 + threadIdx.x;
    int lane = threadIdx.x & 31, wid = threadIdx.x >> 5;
    int v = (i < N_NODES) ? d_deg[i] : 0;
#pragma unroll
    for (int o = 16; o; o >>= 1) v += __shfl_xor_sync(0xffffffffu, v, o);
    if (lane == 0) wsum[wid] = v;
    __syncthreads();
    if (threadIdx.x == 0) {
        int sacc = 0;
#pragma unroll
        for (int q = 0; q < 8; q++) sacc += wsum[q];
        d_bsum[blockIdx.x] = sacc;
    }
}

// ---------------- apply: each block self-scans partials then scans its chunk ----------------
__global__ void bapply_kernel() {
    __shared__ int wsum[8];
    __shared__ int s_base;
    int b = blockIdx.x;
    int tid = threadIdx.x, lane = tid & 31, wid = tid >> 5;

    // prefix of blocks < b (NBLK=196 < 256)
    int pv = (tid < b) ? d_bsum[tid] : 0;
#pragma unroll
    for (int o = 16; o; o >>= 1) pv += __shfl_xor_sync(0xffffffffu, pv, o);
    if (lane == 0) wsum[wid] = pv;
    __syncthreads();
    if (tid == 0) {
        int sacc = 0;
#pragma unroll
        for (int q = 0; q < 8; q++) sacc += wsum[q];
        s_base = sacc;
    }
    __syncthreads();

    // in-block exclusive scan of this 256-element chunk
    int i = b * 256 + tid;
    int v = (i < N_NODES) ? d_deg[i] : 0;
    int inc = v;
#pragma unroll
    for (int o = 1; o < 32; o <<= 1) {
        int t = __shfl_up_sync(0xffffffffu, inc, o);
        if (lane >= o) inc += t;
    }
    if (lane == 31) wsum[wid] = inc;
    __syncthreads();
    if (wid == 0 && lane < 8) {
        int sv = wsum[lane];
        int si = sv;
#pragma unroll
        for (int o = 1; o < 8; o <<= 1) {
            int t = __shfl_up_sync(0x000000ffu, si, o);
            if (lane >= o) si += t;
        }
        wsum[lane] = si - sv;
    }
    __syncthreads();
    if (i < N_NODES) {
        int excl = s_base + wsum[wid] + inc - v;
        d_off[i] = excl;
        d_cur[i] = excl;
    }
    if (i == 0) d_off[N_NODES] = N_EDGES;
}

// ---------------- CSR scatter (int32 reads, 2 edges/thread) ----------------
__global__ void scatter_kernel() {
    int t = blockIdx.x * blockDim.x + threadIdx.x;
    if (2 * t >= N_EDGES) return;
    int2 sv = *(const int2*)(d_src32 + 2 * t);
    int2 dv = *(const int2*)(d_dst32 + 2 * t);
    int p0 = atomicAdd(&d_cur[dv.x], 1);
    int p1 = atomicAdd(&d_cur[dv.y], 1);
    d_csr[p0] = sv.x;
    d_csr[p1] = sv.y;
}

// ---------------- GAT gather (warp per dst, software-pipelined chunks) ----------------
// Lane l owns channels {2l,2l+1} (head l>>2). Chunk of 4 edges: lane layout
// (slot = l>>3, head = l&7). Next chunk's csr+as loads are issued before the
// current chunk's h-gather so the two latency chains overlap.
__global__ void gat_kernel(const float* __restrict__ bias, float* __restrict__ outp,
                           const float* __restrict__ wrel, const float* __restrict__ wroot) {
    int w = (blockIdx.x * blockDim.x + threadIdx.x) >> 5;
    int l = threadIdx.x & 31;
    if (w >= N_NODES) return;
    const int d    = w;
    const int slot = l >> 3;
    const int hl   = l >> 2;
    const int hd   = l & 7;
    const float adv = d_ad[d * 8 + hd];

    int beg   = d_off[d];
    int ne    = d_off[d + 1] - beg;
    int total = ne + 1;                      // + self loop

    float2 acc = make_float2(0.f, 0.f);
    float den = 0.f;

    // prologue: chunk 0
    int src = 0; float ex = 0.f;
    {
        int eidx = slot;
        if (eidx < total) {
            src = (eidx < ne) ? d_csr[beg + eidx] : d;
            float e = d_as[src * 8 + hd] + adv;
            e = fmaxf(e, NEG_SLOPE * e);
            ex = __expf(e);
            den += ex;
        }
    }

    for (int base = 0; base < total; base += 4) {
        int cnt = total - base; if (cnt > 4) cnt = 4;    // warp-uniform
        // prefetch next chunk (overlaps current h loads)
        int neidx = base + 4 + slot;
        bool nv = (neidx < total);
        int nsrc = 0; float nas = 0.f;
        if (nv) {
            nsrc = (neidx < ne) ? d_csr[beg + neidx] : d;
            nas = d_as[nsrc * 8 + hd];
        }
        // consume current chunk
#pragma unroll 4
        for (int s = 0; s < cnt; s++) {
            int ssrc  = __shfl_sync(0xffffffffu, src, s * 8);
            float exc = __shfl_sync(0xffffffffu, ex,  s * 8 + hl);
            float2 hv = *(const float2*)(d_h + (size_t)ssrc * 64 + 2 * l);
            acc.x += hv.x * exc;
            acc.y += hv.y * exc;
        }
        // finish next chunk's exp
        float nex = 0.f;
        if (nv) {
            float e = nas + adv;
            e = fmaxf(e, NEG_SLOPE * e);
            nex = __expf(e);
            den += nex;
        }
        src = nsrc; ex = nex;
    }

    den += __shfl_xor_sync(0xffffffffu, den, 8);
    den += __shfl_xor_sync(0xffffffffu, den, 16);
    float denc = __shfl_sync(0xffffffffu, den, hl) + 1e-16f;

    float bx = bias[2 * l], by = bias[2 * l + 1];
    float2 o = make_float2(acc.x / denc + bx, acc.y / denc + by);
    *(float2*)(outp + (size_t)d * 64 + 2 * l) = o;

    // pooling dot products (linearity trick)
    float wrx = wrel[2 * l],  wry = wrel[2 * l + 1];
    float wox = wroot[2 * l], woy = wroot[2 * l + 1];
    float pr = o.x * wrx + o.y * wry;
    float po = o.x * wox + o.y * woy;
#pragma unroll
    for (int off = 16; off; off >>= 1) {
        pr += __shfl_xor_sync(0xffffffffu, pr, off);
        po += __shfl_xor_sync(0xffffffffu, po, off);
    }
    if (l == 0) { d_prel[d] = pr; d_sroot[d] = po; }
}

// ---------------- pooling score: scalar gather + exp + per-graph denom ----------------
__global__ void score_kernel(const float* __restrict__ brel, const void* __restrict__ batch) {
    int w = (blockIdx.x * blockDim.x + threadIdx.x) >> 5;
    int l = threadIdx.x & 31;
    if (w >= N_NODES) return;
    int d   = w;
    int beg = d_off[d], end = d_off[d + 1];
    float sum = 0.f;
    for (int j = beg + l; j < end; j += 32)
        sum += d_prel[d_csr[j]];
#pragma unroll
    for (int o = 16; o; o >>= 1) sum += __shfl_xor_sync(0xffffffffu, sum, o);
    if (l == 0) {
        float ex = __expf(sum + d_sroot[d] + brel[0]);   // no max-shift: scores bounded
        d_score[d] = ex;
        int w64 = d_w64;
        long long bv = w64 ? ((const long long*)batch)[d] : (long long)((const int*)batch)[d];
        int g = clampi(bv, N_GRAPHS);
        atomicAdd(&d_gden[g], ex);
    }
}

// ---------------- global add pool (sorted batch -> register accumulation) ----------------
// Block = 64 consecutive nodes; thread (c = tid&63, r = tid>>6) accumulates its
// channel over nodes r, r+4, ... flushing one atomic per graph transition.
__global__ void pool_kernel(const void* __restrict__ batch, const float* __restrict__ outp,
                            float* __restrict__ gout) {
    __shared__ float s_s[64];
    __shared__ int   s_g[64];
    int n0  = blockIdx.x * 64;
    int tid = threadIdx.x;
    if (tid < 64) {
        int n = n0 + tid;
        float s = 0.f; int g = -1;
        if (n < N_NODES) {
            int w64 = d_w64;
            long long bv = w64 ? ((const long long*)batch)[n] : (long long)((const int*)batch)[n];
            g = clampi(bv, N_GRAPHS);
            s = d_score[n] / (d_gden[g] + 1e-16f);
        }
        s_s[tid] = s; s_g[tid] = g;
    }
    __syncthreads();
    int c = tid & 63;
    int r = tid >> 6;                 // 0..3
    float acc = 0.f;
    int gcur = -1;
    for (int j = r; j < 64; j += 4) {
        if (n0 + j >= N_NODES) break;
        int g = s_g[j];
        if (g != gcur) {
            if (gcur >= 0) atomicAdd(gout + gcur * 64 + c, acc);
            acc = 0.f; gcur = g;
        }
        acc += outp[(size_t)(n0 + j) * 64 + c] * s_s[j];
    }
    if (gcur >= 0) atomicAdd(gout + gcur * 64 + c, acc);
}

// ---------------- launch ----------------
extern "C" void kernel_launch(void* const* d_in, const int* in_sizes, int n_in,
                              void* d_out, int out_size) {
    const float* x       = (const float*)d_in[0];
    const void*  ei      = d_in[1];
    const void*  batch   = d_in[2];
    const float* W       = (const float*)d_in[3];
    const float* att_src = (const float*)d_in[4];
    const float* att_dst = (const float*)d_in[5];
    const float* bias    = (const float*)d_in[6];
    const float* wrel    = (const float*)d_in[7];
    const float* brel    = (const float*)d_in[8];
    const float* wroot   = (const float*)d_in[9];
    (void)in_sizes; (void)n_in; (void)out_size;

    float* outp = (float*)d_out;
    float* gout = outp + (size_t)N_NODES * OUT_F;

    setup_kernel<<<NBLK, 256>>>((const unsigned int*)ei, gout);
    gemm_kernel<<<(N_NODES + 63) / 64, 256>>>(x, W, att_src, att_dst);
    conv_hist_kernel<<<(N_EDGES / 4 + 255) / 256, 256>>>(ei);
    bsum_kernel<<<NBLK, 256>>>();
    bapply_kernel<<<NBLK, 256>>>();
    scatter_kernel<<<(N_EDGES / 2 + 255) / 256, 256>>>();
    gat_kernel<<<(N_NODES * 32 + 255) / 256, 256>>>(bias, outp, wrel, wroot);
    score_kernel<<<(N_NODES * 32 + 255) / 256, 256>>>(brel, batch);
    pool_kernel<<<(N_NODES + 63) / 64, 256>>>(batch, outp, gout);
}